// round 16
// baseline (speedup 1.0000x reference)
#include <cuda_runtime.h>
#include <cuda_fp16.h>
#include <math.h>
#include <stdint.h>

// Problem constants
#define BB 2
#define LL 1024
#define EE 1024
#define HH 16
#define DD 64
#define NCH 16
#define CHK 64
#define ST_STRIDE 8320
#define ROWS (BB*LL)    // 2048

// GEMM smem (half2 words), BK=64, 2-stage cp.async:
//   A [128 rows][AP=36 words] (32 data words = 64 halves, +4 pad)
//   B [32 k2-rows][BP=136 words]
#define AP 36
#define BP 136
#define AWORDS (128 * AP)          // 4608
#define BWORDS (32 * BP)           // 4352
#define STW (AWORDS + BWORDS)      // 8960 words
#define GSTAGES 2
#define GEMM_SMEM_BYTES (GSTAGES * STW * 4)  // 71680

// Scratch (device globals; no allocs allowed)
__device__ float  g_qkv[ROWS * 3 * EE];
__device__ float  g_h[ROWS * EE];
__device__ float  g_state[BB * HH * NCH * ST_STRIDE];
__device__ __half g_xnh[ROWS * EE];
__device__ __half g_attnh[ROWS * EE];
__device__ __half g_midh[ROWS * 4 * EE];
// packed half2 weights: [k/2][n] words; qkv | out | mlp1 | mlp2
#define WOFF_QKV 0
#define WOFF_OUT (WOFF_QKV + (EE/2) * 3 * EE)
#define WOFF_W1  (WOFF_OUT + (EE/2) * EE)
#define WOFF_W2  (WOFF_W1  + (EE/2) * 4 * EE)
#define WTOTAL   (WOFF_W2  + (2 * EE) * EE)
__device__ uint32_t g_wh[WTOTAL];                  // 24 MB

// segment boundaries in uint4 units for merged wconv
#define SEG0 393216
#define SEG1 524288
#define SEG2 1048576
#define SEG3 1572864

// ---------------------------------------------------------------------------
// helpers
// ---------------------------------------------------------------------------
__device__ __forceinline__ uint32_t pack_h2(float lo, float hi) {
    __half2 h = __floats2half2_rn(lo, hi);
    return *reinterpret_cast<uint32_t*>(&h);
}

__device__ __forceinline__ float gelu_fast(float v) {
    float u = v * (0.7978845608028654f + 0.035677408136300125f * v * v);
    float a = fabsf(u);
    float e = __expf(fminf(2.f * a, 80.f));
    float th = 1.f - __fdividef(2.f, e + 1.f);
    th = copysignf(th, u);
    return 0.5f * v * (1.f + th);
}

__device__ __forceinline__ void mma_f16(float* c, const uint32_t* a,
                                        uint32_t b0, uint32_t b1) {
    asm volatile(
        "mma.sync.aligned.m16n8k16.row.col.f32.f16.f16.f32 "
        "{%0,%1,%2,%3}, {%4,%5,%6,%7}, {%8,%9}, {%0,%1,%2,%3};"
        : "+f"(c[0]), "+f"(c[1]), "+f"(c[2]), "+f"(c[3])
        : "r"(a[0]), "r"(a[1]), "r"(a[2]), "r"(a[3]),
          "r"(b0), "r"(b1));
}

__device__ __forceinline__ void ldsm_x4(uint32_t* d, uint32_t saddr) {
    asm volatile("ldmatrix.sync.aligned.m8n8.x4.shared.b16 {%0,%1,%2,%3}, [%4];"
                 : "=r"(d[0]), "=r"(d[1]), "=r"(d[2]), "=r"(d[3])
                 : "r"(saddr));
}

__device__ __forceinline__ void cpasync16(uint32_t saddr, const void* gptr) {
    asm volatile("cp.async.cg.shared.global [%0], [%1], 16;" :: "r"(saddr), "l"(gptr));
}
__device__ __forceinline__ void cpasync_commit() {
    asm volatile("cp.async.commit_group;" ::: "memory");
}
template <int N>
__device__ __forceinline__ void cpasync_wait() {
    asm volatile("cp.async.wait_group %0;" :: "n"(N) : "memory");
}

// ---------------------------------------------------------------------------
// Merged weight convert: all four weights fp32 [K][N] -> packed half2 [(k/2)][n]
// ---------------------------------------------------------------------------
__global__ void wconv_all(const float* __restrict__ qkv_w,
                          const float* __restrict__ out_w,
                          const float* __restrict__ w1,
                          const float* __restrict__ w2,
                          uint32_t* __restrict__ wh) {
    int idx = blockIdx.x * 256 + threadIdx.x;
    const float* in;
    uint32_t* out;
    int N, li;
    if (idx < SEG0)      { in = qkv_w; out = wh + WOFF_QKV; N = 3 * EE; li = idx; }
    else if (idx < SEG1) { in = out_w; out = wh + WOFF_OUT; N = EE;     li = idx - SEG0; }
    else if (idx < SEG2) { in = w1;    out = wh + WOFF_W1;  N = 4 * EE; li = idx - SEG1; }
    else                 { in = w2;    out = wh + WOFF_W2;  N = EE;     li = idx - SEG2; }
    int nq = N >> 2;
    int r = li / nq;
    int n = (li - r * nq) << 2;
    const float* r0 = in + (size_t)(2 * r) * N + n;
    const float* r1 = r0 + N;
    float4 a = *(const float4*)r0;
    float4 b = *(const float4*)r1;
    uint4 u;
    u.x = pack_h2(a.x, b.x);
    u.y = pack_h2(a.y, b.y);
    u.z = pack_h2(a.z, b.z);
    u.w = pack_h2(a.w, b.w);
    *(uint4*)(out + (size_t)r * N + n) = u;
}

// ---------------------------------------------------------------------------
// FP16 mma.sync GEMM: BK=64, 2-stage cp.async, 1 sync/tile, 2 CTAs/SM.
// 128x128 tile, 8 warps (2x4), warp tile 64x32, 4 k16-steps per tile.
// A: __half [M][K]; Wh: packed half2 words [(K/2)][N].
// epi: 0=bias 1=bias+gelu 2=bias+res. ohalf: write __half output to Ch.
// ---------------------------------------------------------------------------
__global__ void __launch_bounds__(256, 2)
tgemm_kernel(const __half* __restrict__ A, const uint32_t* __restrict__ Wh,
             const float* __restrict__ bias, const float* __restrict__ res,
             float* __restrict__ C, __half* __restrict__ Ch,
             int M, int N, int K, int epi, int ohalf) {
    extern __shared__ uint32_t smu[];
    uint32_t sbase = (uint32_t)__cvta_generic_to_shared(smu);

    int tid = threadIdx.x;
    int bx = blockIdx.x;   // N tile
    int by = blockIdx.y;   // M tile
    int warp = tid >> 5;
    int lane = tid & 31;
    int wm = warp >> 2;    // 0..1 (64 rows)
    int wn = warp & 3;     // 0..3 (32 cols)
    int g  = lane >> 2;    // 0..7
    int tg = lane & 3;     // 0..3

    float acc[4][4][4];
    #pragma unroll
    for (int mi = 0; mi < 4; mi++)
        #pragma unroll
        for (int ni = 0; ni < 4; ni++)
            #pragma unroll
            for (int r = 0; r < 4; r++) acc[mi][ni][r] = 0.f;

    // A copy: row am = tid>>1 (0..127), half offset (tid&1)*32; 4 x 16B
    int am = tid >> 1;
    const __half* Ag = A + (size_t)(by * 128 + am) * K + (tid & 1) * 32;
    uint32_t awByte = (uint32_t)(am * AP + (tid & 1) * 16) * 4u;
    // B copy: k2-row kk = tid>>3 (0..31), n words (tid&7)*16; 4 x 16B
    int kk = tid >> 3;
    int n0c = (tid & 7) * 16;
    const uint32_t* Wg = Wh + (size_t)kk * N + bx * 128 + n0c;
    uint32_t bwByte = (uint32_t)(AWORDS + kk * BP + n0c) * 4u;

    int sel = lane >> 3;
    int rr  = lane & 7;
    int aLaneOff = ((sel & 1) * 8 + rr) * AP + (sel >> 1) * 4;

    int m0base = wm * 64;
    int n0base = wn * 32;
    int nT = K >> 6;

    auto issue = [&](int t) {
        uint32_t s = sbase + (uint32_t)((t & 1) * STW) * 4u;
        const __half* Asrc = Ag + t * 64;
        #pragma unroll
        for (int i = 0; i < 4; i++)
            cpasync16(s + awByte + i * 16u, Asrc + i * 8);
        const uint32_t* Wsrc = Wg + (size_t)(t * 32) * N;
        #pragma unroll
        for (int i = 0; i < 4; i++)
            cpasync16(s + bwByte + i * 16u, Wsrc + i * 4);
    };

    // prologue: tile 0 in flight
    issue(0); cpasync_commit();

    for (int t = 0; t < nT; t++) {
        cpasync_wait<0>();      // tile t resident
        __syncthreads();        // visibility + retire reads of buf (t-1)&1

        if (t + 1 < nT) issue(t + 1);
        cpasync_commit();

        uint32_t sA = sbase + (uint32_t)((t & 1) * STW) * 4u;
        const uint32_t* sB = smu + (t & 1) * STW + AWORDS;

        #pragma unroll
        for (int ks = 0; ks < 4; ks++) {        // four k16 steps
            int kw = ks * 8;                    // word (half2) offset
            uint32_t af[4][4];
            #pragma unroll
            for (int mi = 0; mi < 4; mi++)
                ldsm_x4(af[mi], sA + 4u * (uint32_t)((m0base + mi * 16) * AP + kw + aLaneOff));
            uint32_t bf[4][2];
            #pragma unroll
            for (int ni = 0; ni < 4; ni++) {
                int idx = (kw + tg) * BP + n0base + ni * 8 + g;
                bf[ni][0] = sB[idx];
                bf[ni][1] = sB[idx + 4 * BP];
            }
            #pragma unroll
            for (int mi = 0; mi < 4; mi++)
                #pragma unroll
                for (int ni = 0; ni < 4; ni++)
                    mma_f16(acc[mi][ni], af[mi], bf[ni][0], bf[ni][1]);
        }
    }

    // Epilogue
    #pragma unroll
    for (int mi = 0; mi < 4; mi++) {
        #pragma unroll
        for (int ni = 0; ni < 4; ni++) {
            int col = bx * 128 + wn * 32 + ni * 8 + tg * 2;
            float b0 = bias[col], b1 = bias[col + 1];
            #pragma unroll
            for (int half = 0; half < 2; half++) {
                int orow = by * 128 + wm * 64 + mi * 16 + g + half * 8;
                size_t off = (size_t)orow * N + col;
                float v0 = acc[mi][ni][half * 2 + 0] + b0;
                float v1 = acc[mi][ni][half * 2 + 1] + b1;
                if (epi == 1) {
                    v0 = gelu_fast(v0);
                    v1 = gelu_fast(v1);
                } else if (epi == 2) {
                    v0 += res[off];
                    v1 += res[off + 1];
                }
                if (ohalf) {
                    *(uint32_t*)(Ch + off) = pack_h2(v0, v1);
                } else {
                    *(float2*)(C + off) = make_float2(v0, v1);
                }
            }
        }
    }
}

// ---------------------------------------------------------------------------
// RMSNorm -> __half output (GEMM A input)
// ---------------------------------------------------------------------------
__global__ void rmsnorm_kernel(const float* __restrict__ x,
                               const float* __restrict__ w,
                               __half* __restrict__ out) {
    int row = blockIdx.x;
    int tid = threadIdx.x;
    const float4* xr = (const float4*)(x + (size_t)row * EE);
    float4 v = xr[tid];
    float ss = v.x*v.x + v.y*v.y + v.z*v.z + v.w*v.w;
    #pragma unroll
    for (int o = 16; o; o >>= 1) ss += __shfl_xor_sync(0xffffffffu, ss, o);
    __shared__ float red[8];
    if ((tid & 31) == 0) red[tid >> 5] = ss;
    __syncthreads();
    float tot = 0.f;
    #pragma unroll
    for (int i = 0; i < 8; i++) tot += red[i];
    float scale = rsqrtf(tot * (1.0f / (float)EE) + 1e-6f);
    float4 wv = ((const float4*)w)[tid];
    uint2 o;
    o.x = pack_h2(v.x * scale * wv.x, v.y * scale * wv.y);
    o.y = pack_h2(v.z * scale * wv.z, v.w * scale * wv.w);
    *(uint2*)(out + (size_t)row * EE + tid * 4) = o;
}

// ---------------------------------------------------------------------------
// Attention pass A: per-chunk state sums, register outer product.
// ---------------------------------------------------------------------------
#define CSP 68
__global__ void __launch_bounds__(256)
attn_chunk_state(const float* __restrict__ qkv, float* __restrict__ state) {
    int blk = blockIdx.x;
    int c = blk % NCH;
    int bh = blk / NCH;
    int b = bh / HH, h = bh % HH;

    __shared__ float sk[CHK][CSP];
    __shared__ float sv[CHK][CSP];
    __shared__ float cw[CHK], sw[CHK];

    int tid = threadIdx.x;
    for (int idx = tid; idx < CHK * 16; idx += 256) {
        int j = idx >> 4;
        int dd = (idx & 15) << 2;
        int l = c * CHK + j;
        const float* base = qkv + (size_t)(b * LL + l) * (3 * EE) + h * DD;
        float4 kv = *(const float4*)(base + EE + dd);
        float4 vv = *(const float4*)(base + 2 * EE + dd);
        float4 kr;
        kr.x = fmaxf(kv.x, 0.f); kr.y = fmaxf(kv.y, 0.f);
        kr.z = fmaxf(kv.z, 0.f); kr.w = fmaxf(kv.w, 0.f);
        *(float4*)&sk[j][dd] = kr;
        *(float4*)&sv[j][dd] = vv;
    }
    if (tid < CHK) {
        float ang = 1.5707963267948966f * (float)(c * CHK + tid) / (float)LL;
        cw[tid] = cosf(ang);
        sw[tid] = sinf(ang);
    }
    __syncthreads();

    int eq = (tid & 15) * 4;     // e base
    int dq = (tid >> 4) * 4;     // d base
    float accC[4][4], accS[4][4];
    #pragma unroll
    for (int r = 0; r < 4; r++)
        #pragma unroll
        for (int s = 0; s < 4; s++) { accC[r][s] = 0.f; accS[r][s] = 0.f; }

    for (int j = 0; j < CHK; j++) {
        float4 kd = *(const float4*)&sk[j][dq];
        float4 ve = *(const float4*)&sv[j][eq];
        float cwj = cw[j], swj = sw[j];
        float tc[4], ts[4];
        tc[0] = ve.x * cwj; tc[1] = ve.y * cwj; tc[2] = ve.z * cwj; tc[3] = ve.w * cwj;
        ts[0] = ve.x * swj; ts[1] = ve.y * swj; ts[2] = ve.z * swj; ts[3] = ve.w * swj;
        float kr[4] = {kd.x, kd.y, kd.z, kd.w};
        #pragma unroll
        for (int r = 0; r < 4; r++)
            #pragma unroll
            for (int s = 0; s < 4; s++) {
                accC[r][s] = fmaf(kr[r], tc[s], accC[r][s]);
                accS[r][s] = fmaf(kr[r], ts[s], accS[r][s]);
            }
    }

    float* st = state + ((size_t)bh * NCH + c) * ST_STRIDE;
    #pragma unroll
    for (int r = 0; r < 4; r++) {
        *(float4*)&st[(dq + r) * 64 + eq] =
            make_float4(accC[r][0], accC[r][1], accC[r][2], accC[r][3]);
        *(float4*)&st[4096 + (dq + r) * 64 + eq] =
            make_float4(accS[r][0], accS[r][1], accS[r][2], accS[r][3]);
    }
    if (tid < DD) {
        float zc = 0.f, zs = 0.f;
        for (int j = 0; j < CHK; j++) {
            float kd = sk[j][tid];
            zc = fmaf(kd, cw[j], zc);
            zs = fmaf(kd, sw[j], zs);
        }
        st[8192 + tid] = zc;
        st[8256 + tid] = zs;
    }
}

// ---------------------------------------------------------------------------
// Attention pass B: exclusive prefix over chunks (in-place).
// ---------------------------------------------------------------------------
__global__ void attn_prefix(float* __restrict__ state) {
    int bh  = blockIdx.y;
    int idx = blockIdx.x * 256 + threadIdx.x;
    if (idx >= ST_STRIDE) return;
    float* p = state + (size_t)bh * NCH * ST_STRIDE + idx;
    float vals[NCH];
    #pragma unroll
    for (int cc = 0; cc < NCH; cc++) vals[cc] = p[(size_t)cc * ST_STRIDE];
    float run = 0.f;
    #pragma unroll
    for (int cc = 0; cc < NCH; cc++) {
        p[(size_t)cc * ST_STRIDE] = run;
        run += vals[cc];
    }
}

// ---------------------------------------------------------------------------
// Attention pass C: per-chunk output -> __half (out-proj GEMM A input).
// ---------------------------------------------------------------------------
#define ATTN_SMEM_FLOATS (6 * 64 * 65 + 64 + 64 + 64 + 64 + 256 + 64)
#define ATTN_SMEM_BYTES (ATTN_SMEM_FLOATS * 4)

__global__ void __launch_bounds__(256)
attn_out_kernel(const float* __restrict__ qkv, const float* __restrict__ state,
                __half* __restrict__ out) {
    extern __shared__ float smf[];
    float* sq = smf;
    float* sk = sq + 4160;
    float* sv = sk + 4160;
    float* Sc = sv + 4160;
    float* Ss = Sc + 4160;
    float* AS = Ss + 4160;
    float* cw = AS + 4160;
    float* sw = cw + 64;
    float* Zc = sw + 64;
    float* Zs = Zc + 64;
    float* normp = Zs + 64;
    float* normF = normp + 256;

    int blk = blockIdx.x;
    int c = blk % NCH;
    int bh = blk / NCH;
    int b = bh / HH, h = bh % HH;
    int tid = threadIdx.x;

    const float* st = state + ((size_t)bh * NCH + c) * ST_STRIDE;

    for (int idx = tid; idx < CHK * 16; idx += 256) {
        int j = idx >> 4;
        int dd = (idx & 15) << 2;
        int l = c * CHK + j;
        const float* base = qkv + (size_t)(b * LL + l) * (3 * EE) + h * DD;
        float4 qv = *(const float4*)(base + dd);
        float4 kv = *(const float4*)(base + EE + dd);
        float4 vv = *(const float4*)(base + 2 * EE + dd);
        int ro = j * 65 + dd;
        sq[ro + 0] = fmaxf(qv.x, 0.f); sq[ro + 1] = fmaxf(qv.y, 0.f);
        sq[ro + 2] = fmaxf(qv.z, 0.f); sq[ro + 3] = fmaxf(qv.w, 0.f);
        sk[ro + 0] = fmaxf(kv.x, 0.f); sk[ro + 1] = fmaxf(kv.y, 0.f);
        sk[ro + 2] = fmaxf(kv.z, 0.f); sk[ro + 3] = fmaxf(kv.w, 0.f);
        sv[ro + 0] = vv.x; sv[ro + 1] = vv.y; sv[ro + 2] = vv.z; sv[ro + 3] = vv.w;
        int flat = idx << 2;
        int d = flat >> 6, e = flat & 63;
        float4 scv = *(const float4*)(st + flat);
        float4 ssv = *(const float4*)(st + 4096 + flat);
        int so = d * 65 + e;
        Sc[so + 0] = scv.x; Sc[so + 1] = scv.y; Sc[so + 2] = scv.z; Sc[so + 3] = scv.w;
        Ss[so + 0] = ssv.x; Ss[so + 1] = ssv.y; Ss[so + 2] = ssv.z; Ss[so + 3] = ssv.w;
    }
    if (tid < CHK) {
        float ang = 1.5707963267948966f * (float)(c * CHK + tid) / (float)LL;
        cw[tid] = cosf(ang);
        sw[tid] = sinf(ang);
        Zc[tid] = st[8192 + tid];
        Zs[tid] = st[8256 + tid];
    }
    __syncthreads();

    {
        int jc = tid >> 6;
        int i  = tid & 63;
        float acc[16];
        #pragma unroll
        for (int r = 0; r < 16; r++) acc[r] = 0.f;
        for (int d = 0; d < DD; d++) {
            float qv = sq[i * 65 + d];
            #pragma unroll
            for (int r = 0; r < 16; r++)
                acc[r] = fmaf(qv, sk[(jc * 16 + r) * 65 + d], acc[r]);
        }
        float cwi = cw[i], swi = sw[i];
        float rsum = 0.f;
        #pragma unroll
        for (int r = 0; r < 16; r++) {
            int j = jc * 16 + r;
            float wgt = (j <= i) ? (cwi * cw[j] + swi * sw[j]) : 0.f;
            float a = acc[r] * wgt;
            AS[i * 65 + j] = a;
            rsum += a;
        }
        normp[jc * 64 + i] = rsum;
    }
    __syncthreads();

    if (tid < 64) {
        int i = tid;
        float n = normp[i] + normp[64 + i] + normp[128 + i] + normp[192 + i];
        float dc = 0.f, ds = 0.f;
        for (int d = 0; d < DD; d++) {
            float qv = sq[i * 65 + d];
            dc = fmaf(qv, Zc[d], dc);
            ds = fmaf(qv, Zs[d], ds);
        }
        normF[i] = n + cw[i] * dc + sw[i] * ds;
    }

    int ec = tid >> 6;
    int i2 = tid & 63;
    int e0 = ec * 16;
    float accO[16], accC2[16], accS2[16];
    #pragma unroll
    for (int r = 0; r < 16; r++) { accO[r] = 0.f; accC2[r] = 0.f; accS2[r] = 0.f; }

    for (int j = 0; j < CHK; j++) {
        float av = AS[i2 * 65 + j];
        #pragma unroll
        for (int r = 0; r < 16; r++)
            accO[r] = fmaf(av, sv[j * 65 + e0 + r], accO[r]);
    }
    for (int d = 0; d < DD; d++) {
        float qv = sq[i2 * 65 + d];
        #pragma unroll
        for (int r = 0; r < 16; r++) {
            accC2[r] = fmaf(qv, Sc[d * 65 + e0 + r], accC2[r]);
            accS2[r] = fmaf(qv, Ss[d * 65 + e0 + r], accS2[r]);
        }
    }
    __syncthreads();

    float nrm = normF[i2] + 1e-6f;
    float inv = 1.0f / nrm;
    float cwi = cw[i2], swi = sw[i2];
    int lg = c * CHK + i2;
    __half* op = out + (size_t)(b * LL + lg) * EE + h * DD + e0;
    #pragma unroll
    for (int r4 = 0; r4 < 4; r4++) {
        float v0 = (accO[r4*4+0] + cwi*accC2[r4*4+0] + swi*accS2[r4*4+0]) * inv;
        float v1 = (accO[r4*4+1] + cwi*accC2[r4*4+1] + swi*accS2[r4*4+1]) * inv;
        float v2 = (accO[r4*4+2] + cwi*accC2[r4*4+2] + swi*accS2[r4*4+2]) * inv;
        float v3 = (accO[r4*4+3] + cwi*accC2[r4*4+3] + swi*accS2[r4*4+3]) * inv;
        uint2 o;
        o.x = pack_h2(v0, v1);
        o.y = pack_h2(v2, v3);
        *(uint2*)(op + r4 * 4) = o;
    }
}

// ---------------------------------------------------------------------------
// launch
// ---------------------------------------------------------------------------
extern "C" void kernel_launch(void* const* d_in, const int* in_sizes, int n_in,
                              void* d_out, int out_size) {
    const float* x       = (const float*)d_in[0];
    const float* qkv_w   = (const float*)d_in[1];
    const float* qkv_b   = (const float*)d_in[2];
    const float* out_w   = (const float*)d_in[3];
    const float* out_b   = (const float*)d_in[4];
    const float* norm1_w = (const float*)d_in[5];
    const float* norm2_w = (const float*)d_in[6];
    const float* mlp_w1  = (const float*)d_in[7];
    const float* mlp_b1  = (const float*)d_in[8];
    const float* mlp_w2  = (const float*)d_in[9];
    const float* mlp_b2  = (const float*)d_in[10];
    float* out = (float*)d_out;

    float *qkv, *hbuf, *state;
    __half *xnh, *attnh, *midh;
    uint32_t* wh;
    cudaGetSymbolAddress((void**)&qkv, g_qkv);
    cudaGetSymbolAddress((void**)&hbuf, g_h);
    cudaGetSymbolAddress((void**)&state, g_state);
    cudaGetSymbolAddress((void**)&xnh, g_xnh);
    cudaGetSymbolAddress((void**)&attnh, g_attnh);
    cudaGetSymbolAddress((void**)&midh, g_midh);
    cudaGetSymbolAddress((void**)&wh, g_wh);

    cudaFuncSetAttribute(attn_out_kernel,
                         cudaFuncAttributeMaxDynamicSharedMemorySize,
                         ATTN_SMEM_BYTES);
    cudaFuncSetAttribute(tgemm_kernel,
                         cudaFuncAttributeMaxDynamicSharedMemorySize,
                         GEMM_SMEM_BYTES);

    // 0. pack all weights to half2 [(k/2)][n] in ONE launch
    wconv_all<<<SEG3 / 256, 256>>>(qkv_w, out_w, mlp_w1, mlp_w2, wh);

    // 1. xnh = half(rmsnorm(x, norm1_w))
    rmsnorm_kernel<<<ROWS, 256>>>(x, norm1_w, xnh);
    // 2. qkv = xnh @ qkv_w + qkv_b (fp32 out for attention)
    tgemm_kernel<<<dim3(3 * EE / 128, ROWS / 128), 256, GEMM_SMEM_BYTES>>>(
        xnh, wh + WOFF_QKV, qkv_b, nullptr, qkv, nullptr, ROWS, 3 * EE, EE, 0, 0);
    // 3-5. cosformer attention (chunked); attnh emitted as half
    attn_chunk_state<<<BB * HH * NCH, 256>>>(qkv, state);
    attn_prefix<<<dim3((ST_STRIDE + 255) / 256, BB * HH), 256>>>(state);
    attn_out_kernel<<<BB * HH * NCH, 256, ATTN_SMEM_BYTES>>>(qkv, state, attnh);
    // 6. h = attnh @ out_w + out_b + x (fp32)
    tgemm_kernel<<<dim3(EE / 128, ROWS / 128), 256, GEMM_SMEM_BYTES>>>(
        attnh, wh + WOFF_OUT, out_b, x, hbuf, nullptr, ROWS, EE, EE, 2, 0);
    // 7. xnh = half(rmsnorm(h, norm2_w))
    rmsnorm_kernel<<<ROWS, 256>>>(hbuf, norm2_w, xnh);
    // 8. midh = half(gelu(xnh @ mlp_w1 + mlp_b1))
    tgemm_kernel<<<dim3(4 * EE / 128, ROWS / 128), 256, GEMM_SMEM_BYTES>>>(
        xnh, wh + WOFF_W1, mlp_b1, nullptr, nullptr, midh, ROWS, 4 * EE, EE, 1, 1);
    // 9. out = midh @ mlp_w2 + mlp_b2 + h (fp32 final)
    tgemm_kernel<<<dim3(EE / 128, ROWS / 128), 256, GEMM_SMEM_BYTES>>>(
        midh, wh + WOFF_W2, mlp_b2, hbuf, out, nullptr, ROWS, EE, 4 * EE, 2, 0);
}

// round 17
// speedup vs baseline: 1.0700x; 1.0700x over previous
#include <cuda_runtime.h>
#include <cuda_fp16.h>
#include <math.h>
#include <stdint.h>

// Problem constants
#define BB 2
#define LL 1024
#define EE 1024
#define HH 16
#define DD 64
#define NCH 16
#define CHK 64
#define ST_STRIDE 8320
#define ROWS (BB*LL)    // 2048

// GEMM smem (half2 words), 3-stage cp.async pipeline:
//   A [128 rows][AP=20 words], B [16 k2-rows][BP=136 words]
#define AP 20
#define BP 136
#define AWORDS (128 * AP)          // 2560
#define BWORDS (16 * BP)           // 2176
#define STW (AWORDS + BWORDS)      // 4736 words
#define GSTAGES 3
#define GEMM_SMEM_BYTES (GSTAGES * STW * 4)  // 56832

// Scratch (device globals; no allocs allowed)
__device__ float  g_qkv[ROWS * 3 * EE];
__device__ float  g_h[ROWS * EE];
__device__ float  g_state[BB * HH * NCH * ST_STRIDE];
__device__ __half g_xnh[ROWS * EE];
__device__ __half g_attnh[ROWS * EE];
__device__ __half g_midh[ROWS * 4 * EE];
// packed half2 weights: [k/2][n] words; qkv | out | mlp1 | mlp2
#define WOFF_QKV 0
#define WOFF_OUT (WOFF_QKV + (EE/2) * 3 * EE)
#define WOFF_W1  (WOFF_OUT + (EE/2) * EE)
#define WOFF_W2  (WOFF_W1  + (EE/2) * 4 * EE)
#define WTOTAL   (WOFF_W2  + (2 * EE) * EE)
__device__ uint32_t g_wh[WTOTAL];                  // 24 MB

// segment boundaries in uint4 units for merged wconv
#define SEG0 393216
#define SEG1 524288
#define SEG2 1048576
#define SEG3 1572864
#define WHALF (SEG3 / 2)

// ---------------------------------------------------------------------------
// helpers
// ---------------------------------------------------------------------------
__device__ __forceinline__ uint32_t pack_h2(float lo, float hi) {
    __half2 h = __floats2half2_rn(lo, hi);
    return *reinterpret_cast<uint32_t*>(&h);
}

__device__ __forceinline__ float gelu_fast(float v) {
    float u = v * (0.7978845608028654f + 0.035677408136300125f * v * v);
    float a = fabsf(u);
    float e = __expf(fminf(2.f * a, 80.f));
    float th = 1.f - __fdividef(2.f, e + 1.f);
    th = copysignf(th, u);
    return 0.5f * v * (1.f + th);
}

__device__ __forceinline__ void mma_f16(float* c, const uint32_t* a,
                                        uint32_t b0, uint32_t b1) {
    asm volatile(
        "mma.sync.aligned.m16n8k16.row.col.f32.f16.f16.f32 "
        "{%0,%1,%2,%3}, {%4,%5,%6,%7}, {%8,%9}, {%0,%1,%2,%3};"
        : "+f"(c[0]), "+f"(c[1]), "+f"(c[2]), "+f"(c[3])
        : "r"(a[0]), "r"(a[1]), "r"(a[2]), "r"(a[3]),
          "r"(b0), "r"(b1));
}

__device__ __forceinline__ void ldsm_x4(uint32_t* d, uint32_t saddr) {
    asm volatile("ldmatrix.sync.aligned.m8n8.x4.shared.b16 {%0,%1,%2,%3}, [%4];"
                 : "=r"(d[0]), "=r"(d[1]), "=r"(d[2]), "=r"(d[3])
                 : "r"(saddr));
}

__device__ __forceinline__ void cpasync16(uint32_t saddr, const void* gptr) {
    asm volatile("cp.async.cg.shared.global [%0], [%1], 16;" :: "r"(saddr), "l"(gptr));
}
__device__ __forceinline__ void cpasync_commit() {
    asm volatile("cp.async.commit_group;" ::: "memory");
}
template <int N>
__device__ __forceinline__ void cpasync_wait() {
    asm volatile("cp.async.wait_group %0;" :: "n"(N) : "memory");
}

// ---------------------------------------------------------------------------
// Merged weight convert, 2 independent uint4 tasks per thread (MLP boost):
// all four weights fp32 [K][N] -> packed half2 [(k/2)][n]
// ---------------------------------------------------------------------------
__device__ __forceinline__ void wconv_one(int idx,
                                          const float* __restrict__ qkv_w,
                                          const float* __restrict__ out_w,
                                          const float* __restrict__ w1,
                                          const float* __restrict__ w2,
                                          uint32_t* __restrict__ wh) {
    const float* in;
    uint32_t* out;
    int N, li;
    if (idx < SEG0)      { in = qkv_w; out = wh + WOFF_QKV; N = 3 * EE; li = idx; }
    else if (idx < SEG1) { in = out_w; out = wh + WOFF_OUT; N = EE;     li = idx - SEG0; }
    else if (idx < SEG2) { in = w1;    out = wh + WOFF_W1;  N = 4 * EE; li = idx - SEG1; }
    else                 { in = w2;    out = wh + WOFF_W2;  N = EE;     li = idx - SEG2; }
    int nq = N >> 2;
    int r = li / nq;
    int n = (li - r * nq) << 2;
    const float* r0 = in + (size_t)(2 * r) * N + n;
    const float* r1 = r0 + N;
    float4 a = *(const float4*)r0;
    float4 b = *(const float4*)r1;
    uint4 u;
    u.x = pack_h2(a.x, b.x);
    u.y = pack_h2(a.y, b.y);
    u.z = pack_h2(a.z, b.z);
    u.w = pack_h2(a.w, b.w);
    *(uint4*)(out + (size_t)r * N + n) = u;
}

__global__ void wconv_all(const float* __restrict__ qkv_w,
                          const float* __restrict__ out_w,
                          const float* __restrict__ w1,
                          const float* __restrict__ w2,
                          uint32_t* __restrict__ wh) {
    int idx = blockIdx.x * 256 + threadIdx.x;
    wconv_one(idx, qkv_w, out_w, w1, w2, wh);
    wconv_one(idx + WHALF, qkv_w, out_w, w1, w2, wh);
}

// ---------------------------------------------------------------------------
// FP16 mma.sync GEMM (R15 winner): 3-stage cp.async, BK=32, 1 sync/tile,
// 2 CTAs/SM. 128x128 tile, 8 warps (2x4), warp tile 64x32.
// epi: 0=bias 1=bias+gelu 2=bias+res. ohalf: write __half output to Ch.
// ---------------------------------------------------------------------------
__global__ void __launch_bounds__(256, 2)
tgemm_kernel(const __half* __restrict__ A, const uint32_t* __restrict__ Wh,
             const float* __restrict__ bias, const float* __restrict__ res,
             float* __restrict__ C, __half* __restrict__ Ch,
             int M, int N, int K, int epi, int ohalf) {
    extern __shared__ uint32_t smu[];
    uint32_t sbase = (uint32_t)__cvta_generic_to_shared(smu);

    int tid = threadIdx.x;
    int bx = blockIdx.x;   // N tile
    int by = blockIdx.y;   // M tile
    int warp = tid >> 5;
    int lane = tid & 31;
    int wm = warp >> 2;    // 0..1 (64 rows)
    int wn = warp & 3;     // 0..3 (32 cols)
    int g  = lane >> 2;    // 0..7
    int tg = lane & 3;     // 0..3

    float acc[4][4][4];
    #pragma unroll
    for (int mi = 0; mi < 4; mi++)
        #pragma unroll
        for (int ni = 0; ni < 4; ni++)
            #pragma unroll
            for (int r = 0; r < 4; r++) acc[mi][ni][r] = 0.f;

    int am = tid >> 1;
    const __half* Ag = A + (size_t)(by * 128 + am) * K + (tid & 1) * 16;
    uint32_t awByte = (uint32_t)(am * AP + (tid & 1) * 8) * 4u;
    int kk = tid >> 4;
    int n0c = (tid & 15) * 8;
    const uint32_t* Wg = Wh + (size_t)kk * N + bx * 128 + n0c;
    uint32_t bwByte = (uint32_t)(AWORDS + kk * BP + n0c) * 4u;

    int sel = lane >> 3;
    int rr  = lane & 7;
    int aLaneOff = ((sel & 1) * 8 + rr) * AP + (sel >> 1) * 4;

    int m0base = wm * 64;
    int n0base = wn * 32;
    int nT = K >> 5;

    auto issue = [&](int t) {
        uint32_t s = sbase + (uint32_t)((t % GSTAGES) * STW) * 4u;
        const __half* Asrc = Ag + t * 32;
        cpasync16(s + awByte,       Asrc);
        cpasync16(s + awByte + 16u, Asrc + 8);
        const uint32_t* Wsrc = Wg + (size_t)(t * 16) * N;
        cpasync16(s + bwByte,       Wsrc);
        cpasync16(s + bwByte + 16u, Wsrc + 4);
    };

    // prologue: tiles 0,1 in flight
    issue(0); cpasync_commit();
    issue(1); cpasync_commit();

    for (int t = 0; t < nT; t++) {
        cpasync_wait<1>();      // tile t resident
        __syncthreads();        // visibility + retire reads of buf (t-1)%3

        if (t + 2 < nT) issue(t + 2);
        cpasync_commit();

        uint32_t sA = sbase + (uint32_t)((t % GSTAGES) * STW) * 4u;
        const uint32_t* sB = smu + (t % GSTAGES) * STW + AWORDS;

        #pragma unroll
        for (int ks = 0; ks < 2; ks++) {
            int kw = ks * 8;
            uint32_t af[4][4];
            #pragma unroll
            for (int mi = 0; mi < 4; mi++)
                ldsm_x4(af[mi], sA + 4u * (uint32_t)((m0base + mi * 16) * AP + kw + aLaneOff));
            uint32_t bf[4][2];
            #pragma unroll
            for (int ni = 0; ni < 4; ni++) {
                int idx = (kw + tg) * BP + n0base + ni * 8 + g;
                bf[ni][0] = sB[idx];
                bf[ni][1] = sB[idx + 4 * BP];
            }
            #pragma unroll
            for (int mi = 0; mi < 4; mi++)
                #pragma unroll
                for (int ni = 0; ni < 4; ni++)
                    mma_f16(acc[mi][ni], af[mi], bf[ni][0], bf[ni][1]);
        }
    }

    // Epilogue
    #pragma unroll
    for (int mi = 0; mi < 4; mi++) {
        #pragma unroll
        for (int ni = 0; ni < 4; ni++) {
            int col = bx * 128 + wn * 32 + ni * 8 + tg * 2;
            float b0 = bias[col], b1 = bias[col + 1];
            #pragma unroll
            for (int half = 0; half < 2; half++) {
                int orow = by * 128 + wm * 64 + mi * 16 + g + half * 8;
                size_t off = (size_t)orow * N + col;
                float v0 = acc[mi][ni][half * 2 + 0] + b0;
                float v1 = acc[mi][ni][half * 2 + 1] + b1;
                if (epi == 1) {
                    v0 = gelu_fast(v0);
                    v1 = gelu_fast(v1);
                } else if (epi == 2) {
                    v0 += res[off];
                    v1 += res[off + 1];
                }
                if (ohalf) {
                    *(uint32_t*)(Ch + off) = pack_h2(v0, v1);
                } else {
                    *(float2*)(C + off) = make_float2(v0, v1);
                }
            }
        }
    }
}

// ---------------------------------------------------------------------------
// RMSNorm -> __half output, two rows per block (512 threads)
// ---------------------------------------------------------------------------
__global__ void __launch_bounds__(512)
rmsnorm_kernel(const float* __restrict__ x, const float* __restrict__ w,
               __half* __restrict__ out) {
    int row = blockIdx.x * 2 + (threadIdx.x >> 8);
    int tid = threadIdx.x & 255;
    const float4* xr = (const float4*)(x + (size_t)row * EE);
    float4 v = xr[tid];
    float ss = v.x*v.x + v.y*v.y + v.z*v.z + v.w*v.w;
    #pragma unroll
    for (int o = 16; o; o >>= 1) ss += __shfl_xor_sync(0xffffffffu, ss, o);
    __shared__ float red[16];
    int wid = threadIdx.x >> 5;
    if ((threadIdx.x & 31) == 0) red[wid] = ss;
    __syncthreads();
    int base = (threadIdx.x >> 8) * 8;
    float tot = 0.f;
    #pragma unroll
    for (int i = 0; i < 8; i++) tot += red[base + i];
    float scale = rsqrtf(tot * (1.0f / (float)EE) + 1e-6f);
    float4 wv = ((const float4*)w)[tid];
    uint2 o;
    o.x = pack_h2(v.x * scale * wv.x, v.y * scale * wv.y);
    o.y = pack_h2(v.z * scale * wv.z, v.w * scale * wv.w);
    *(uint2*)(out + (size_t)row * EE + tid * 4) = o;
}

// ---------------------------------------------------------------------------
// Attention pass A: per-chunk state sums, register outer product.
// ---------------------------------------------------------------------------
#define CSP 68
__global__ void __launch_bounds__(256)
attn_chunk_state(const float* __restrict__ qkv, float* __restrict__ state) {
    int blk = blockIdx.x;
    int c = blk % NCH;
    int bh = blk / NCH;
    int b = bh / HH, h = bh % HH;

    __shared__ float sk[CHK][CSP];
    __shared__ float sv[CHK][CSP];
    __shared__ float cw[CHK], sw[CHK];

    int tid = threadIdx.x;
    for (int idx = tid; idx < CHK * 16; idx += 256) {
        int j = idx >> 4;
        int dd = (idx & 15) << 2;
        int l = c * CHK + j;
        const float* base = qkv + (size_t)(b * LL + l) * (3 * EE) + h * DD;
        float4 kv = *(const float4*)(base + EE + dd);
        float4 vv = *(const float4*)(base + 2 * EE + dd);
        float4 kr;
        kr.x = fmaxf(kv.x, 0.f); kr.y = fmaxf(kv.y, 0.f);
        kr.z = fmaxf(kv.z, 0.f); kr.w = fmaxf(kv.w, 0.f);
        *(float4*)&sk[j][dd] = kr;
        *(float4*)&sv[j][dd] = vv;
    }
    if (tid < CHK) {
        float ang = 1.5707963267948966f * (float)(c * CHK + tid) / (float)LL;
        cw[tid] = cosf(ang);
        sw[tid] = sinf(ang);
    }
    __syncthreads();

    int eq = (tid & 15) * 4;
    int dq = (tid >> 4) * 4;
    float accC[4][4], accS[4][4];
    #pragma unroll
    for (int r = 0; r < 4; r++)
        #pragma unroll
        for (int s = 0; s < 4; s++) { accC[r][s] = 0.f; accS[r][s] = 0.f; }

    for (int j = 0; j < CHK; j++) {
        float4 kd = *(const float4*)&sk[j][dq];
        float4 ve = *(const float4*)&sv[j][eq];
        float cwj = cw[j], swj = sw[j];
        float tc[4], ts[4];
        tc[0] = ve.x * cwj; tc[1] = ve.y * cwj; tc[2] = ve.z * cwj; tc[3] = ve.w * cwj;
        ts[0] = ve.x * swj; ts[1] = ve.y * swj; ts[2] = ve.z * swj; ts[3] = ve.w * swj;
        float kr[4] = {kd.x, kd.y, kd.z, kd.w};
        #pragma unroll
        for (int r = 0; r < 4; r++)
            #pragma unroll
            for (int s = 0; s < 4; s++) {
                accC[r][s] = fmaf(kr[r], tc[s], accC[r][s]);
                accS[r][s] = fmaf(kr[r], ts[s], accS[r][s]);
            }
    }

    float* st = state + ((size_t)bh * NCH + c) * ST_STRIDE;
    #pragma unroll
    for (int r = 0; r < 4; r++) {
        *(float4*)&st[(dq + r) * 64 + eq] =
            make_float4(accC[r][0], accC[r][1], accC[r][2], accC[r][3]);
        *(float4*)&st[4096 + (dq + r) * 64 + eq] =
            make_float4(accS[r][0], accS[r][1], accS[r][2], accS[r][3]);
    }
    if (tid < DD) {
        float zc = 0.f, zs = 0.f;
        for (int j = 0; j < CHK; j++) {
            float kd = sk[j][tid];
            zc = fmaf(kd, cw[j], zc);
            zs = fmaf(kd, sw[j], zs);
        }
        st[8192 + tid] = zc;
        st[8256 + tid] = zs;
    }
}

// ---------------------------------------------------------------------------
// Attention pass B: exclusive prefix over chunks (in-place).
// ---------------------------------------------------------------------------
__global__ void attn_prefix(float* __restrict__ state) {
    int bh  = blockIdx.y;
    int idx = blockIdx.x * 256 + threadIdx.x;
    if (idx >= ST_STRIDE) return;
    float* p = state + (size_t)bh * NCH * ST_STRIDE + idx;
    float vals[NCH];
    #pragma unroll
    for (int cc = 0; cc < NCH; cc++) vals[cc] = p[(size_t)cc * ST_STRIDE];
    float run = 0.f;
    #pragma unroll
    for (int cc = 0; cc < NCH; cc++) {
        p[(size_t)cc * ST_STRIDE] = run;
        run += vals[cc];
    }
}

// ---------------------------------------------------------------------------
// Attention pass C: per-chunk output -> __half (out-proj GEMM A input).
// ---------------------------------------------------------------------------
#define ATTN_SMEM_FLOATS (6 * 64 * 65 + 64 + 64 + 64 + 64 + 256 + 64)
#define ATTN_SMEM_BYTES (ATTN_SMEM_FLOATS * 4)

__global__ void __launch_bounds__(256)
attn_out_kernel(const float* __restrict__ qkv, const float* __restrict__ state,
                __half* __restrict__ out) {
    extern __shared__ float smf[];
    float* sq = smf;
    float* sk = sq + 4160;
    float* sv = sk + 4160;
    float* Sc = sv + 4160;
    float* Ss = Sc + 4160;
    float* AS = Ss + 4160;
    float* cw = AS + 4160;
    float* sw = cw + 64;
    float* Zc = sw + 64;
    float* Zs = Zc + 64;
    float* normp = Zs + 64;
    float* normF = normp + 256;

    int blk = blockIdx.x;
    int c = blk % NCH;
    int bh = blk / NCH;
    int b = bh / HH, h = bh % HH;
    int tid = threadIdx.x;

    const float* st = state + ((size_t)bh * NCH + c) * ST_STRIDE;

    for (int idx = tid; idx < CHK * 16; idx += 256) {
        int j = idx >> 4;
        int dd = (idx & 15) << 2;
        int l = c * CHK + j;
        const float* base = qkv + (size_t)(b * LL + l) * (3 * EE) + h * DD;
        float4 qv = *(const float4*)(base + dd);
        float4 kv = *(const float4*)(base + EE + dd);
        float4 vv = *(const float4*)(base + 2 * EE + dd);
        int ro = j * 65 + dd;
        sq[ro + 0] = fmaxf(qv.x, 0.f); sq[ro + 1] = fmaxf(qv.y, 0.f);
        sq[ro + 2] = fmaxf(qv.z, 0.f); sq[ro + 3] = fmaxf(qv.w, 0.f);
        sk[ro + 0] = fmaxf(kv.x, 0.f); sk[ro + 1] = fmaxf(kv.y, 0.f);
        sk[ro + 2] = fmaxf(kv.z, 0.f); sk[ro + 3] = fmaxf(kv.w, 0.f);
        sv[ro + 0] = vv.x; sv[ro + 1] = vv.y; sv[ro + 2] = vv.z; sv[ro + 3] = vv.w;
        int flat = idx << 2;
        int d = flat >> 6, e = flat & 63;
        float4 scv = *(const float4*)(st + flat);
        float4 ssv = *(const float4*)(st + 4096 + flat);
        int so = d * 65 + e;
        Sc[so + 0] = scv.x; Sc[so + 1] = scv.y; Sc[so + 2] = scv.z; Sc[so + 3] = scv.w;
        Ss[so + 0] = ssv.x; Ss[so + 1] = ssv.y; Ss[so + 2] = ssv.z; Ss[so + 3] = ssv.w;
    }
    if (tid < CHK) {
        float ang = 1.5707963267948966f * (float)(c * CHK + tid) / (float)LL;
        cw[tid] = cosf(ang);
        sw[tid] = sinf(ang);
        Zc[tid] = st[8192 + tid];
        Zs[tid] = st[8256 + tid];
    }
    __syncthreads();

    {
        int jc = tid >> 6;
        int i  = tid & 63;
        float acc[16];
        #pragma unroll
        for (int r = 0; r < 16; r++) acc[r] = 0.f;
        for (int d = 0; d < DD; d++) {
            float qv = sq[i * 65 + d];
            #pragma unroll
            for (int r = 0; r < 16; r++)
                acc[r] = fmaf(qv, sk[(jc * 16 + r) * 65 + d], acc[r]);
        }
        float cwi = cw[i], swi = sw[i];
        float rsum = 0.f;
        #pragma unroll
        for (int r = 0; r < 16; r++) {
            int j = jc * 16 + r;
            float wgt = (j <= i) ? (cwi * cw[j] + swi * sw[j]) : 0.f;
            float a = acc[r] * wgt;
            AS[i * 65 + j] = a;
            rsum += a;
        }
        normp[jc * 64 + i] = rsum;
    }
    __syncthreads();

    if (tid < 64) {
        int i = tid;
        float n = normp[i] + normp[64 + i] + normp[128 + i] + normp[192 + i];
        float dc = 0.f, ds = 0.f;
        for (int d = 0; d < DD; d++) {
            float qv = sq[i * 65 + d];
            dc = fmaf(qv, Zc[d], dc);
            ds = fmaf(qv, Zs[d], ds);
        }
        normF[i] = n + cw[i] * dc + sw[i] * ds;
    }

    int ec = tid >> 6;
    int i2 = tid & 63;
    int e0 = ec * 16;
    float accO[16], accC2[16], accS2[16];
    #pragma unroll
    for (int r = 0; r < 16; r++) { accO[r] = 0.f; accC2[r] = 0.f; accS2[r] = 0.f; }

    for (int j = 0; j < CHK; j++) {
        float av = AS[i2 * 65 + j];
        #pragma unroll
        for (int r = 0; r < 16; r++)
            accO[r] = fmaf(av, sv[j * 65 + e0 + r], accO[r]);
    }
    for (int d = 0; d < DD; d++) {
        float qv = sq[i2 * 65 + d];
        #pragma unroll
        for (int r = 0; r < 16; r++) {
            accC2[r] = fmaf(qv, Sc[d * 65 + e0 + r], accC2[r]);
            accS2[r] = fmaf(qv, Ss[d * 65 + e0 + r], accS2[r]);
        }
    }
    __syncthreads();

    float nrm = normF[i2] + 1e-6f;
    float inv = 1.0f / nrm;
    float cwi = cw[i2], swi = sw[i2];
    int lg = c * CHK + i2;
    __half* op = out + (size_t)(b * LL + lg) * EE + h * DD + e0;
    #pragma unroll
    for (int r4 = 0; r4 < 4; r4++) {
        float v0 = (accO[r4*4+0] + cwi*accC2[r4*4+0] + swi*accS2[r4*4+0]) * inv;
        float v1 = (accO[r4*4+1] + cwi*accC2[r4*4+1] + swi*accS2[r4*4+1]) * inv;
        float v2 = (accO[r4*4+2] + cwi*accC2[r4*4+2] + swi*accS2[r4*4+2]) * inv;
        float v3 = (accO[r4*4+3] + cwi*accC2[r4*4+3] + swi*accS2[r4*4+3]) * inv;
        uint2 o;
        o.x = pack_h2(v0, v1);
        o.y = pack_h2(v2, v3);
        *(uint2*)(op + r4 * 4) = o;
    }
}

// ---------------------------------------------------------------------------
// launch
// ---------------------------------------------------------------------------
extern "C" void kernel_launch(void* const* d_in, const int* in_sizes, int n_in,
                              void* d_out, int out_size) {
    const float* x       = (const float*)d_in[0];
    const float* qkv_w   = (const float*)d_in[1];
    const float* qkv_b   = (const float*)d_in[2];
    const float* out_w   = (const float*)d_in[3];
    const float* out_b   = (const float*)d_in[4];
    const float* norm1_w = (const float*)d_in[5];
    const float* norm2_w = (const float*)d_in[6];
    const float* mlp_w1  = (const float*)d_in[7];
    const float* mlp_b1  = (const float*)d_in[8];
    const float* mlp_w2  = (const float*)d_in[9];
    const float* mlp_b2  = (const float*)d_in[10];
    float* out = (float*)d_out;

    float *qkv, *hbuf, *state;
    __half *xnh, *attnh, *midh;
    uint32_t* wh;
    cudaGetSymbolAddress((void**)&qkv, g_qkv);
    cudaGetSymbolAddress((void**)&hbuf, g_h);
    cudaGetSymbolAddress((void**)&state, g_state);
    cudaGetSymbolAddress((void**)&xnh, g_xnh);
    cudaGetSymbolAddress((void**)&attnh, g_attnh);
    cudaGetSymbolAddress((void**)&midh, g_midh);
    cudaGetSymbolAddress((void**)&wh, g_wh);

    cudaFuncSetAttribute(attn_out_kernel,
                         cudaFuncAttributeMaxDynamicSharedMemorySize,
                         ATTN_SMEM_BYTES);
    cudaFuncSetAttribute(tgemm_kernel,
                         cudaFuncAttributeMaxDynamicSharedMemorySize,
                         GEMM_SMEM_BYTES);

    // 0. pack all weights to half2 [(k/2)][n] in ONE launch (2 tasks/thread)
    wconv_all<<<WHALF / 256, 256>>>(qkv_w, out_w, mlp_w1, mlp_w2, wh);

    // 1. xnh = half(rmsnorm(x, norm1_w))
    rmsnorm_kernel<<<ROWS / 2, 512>>>(x, norm1_w, xnh);
    // 2. qkv = xnh @ qkv_w + qkv_b (fp32 out for attention)
    tgemm_kernel<<<dim3(3 * EE / 128, ROWS / 128), 256, GEMM_SMEM_BYTES>>>(
        xnh, wh + WOFF_QKV, qkv_b, nullptr, qkv, nullptr, ROWS, 3 * EE, EE, 0, 0);
    // 3-5. cosformer attention (chunked); attnh emitted as half
    attn_chunk_state<<<BB * HH * NCH, 256>>>(qkv, state);
    attn_prefix<<<dim3((ST_STRIDE + 255) / 256, BB * HH), 256>>>(state);
    attn_out_kernel<<<BB * HH * NCH, 256, ATTN_SMEM_BYTES>>>(qkv, state, attnh);
    // 6. h = attnh @ out_w + out_b + x (fp32)
    tgemm_kernel<<<dim3(EE / 128, ROWS / 128), 256, GEMM_SMEM_BYTES>>>(
        attnh, wh + WOFF_OUT, out_b, x, hbuf, nullptr, ROWS, EE, EE, 2, 0);
    // 7. xnh = half(rmsnorm(h, norm2_w))
    rmsnorm_kernel<<<ROWS / 2, 512>>>(hbuf, norm2_w, xnh);
    // 8. midh = half(gelu(xnh @ mlp_w1 + mlp_b1))
    tgemm_kernel<<<dim3(4 * EE / 128, ROWS / 128), 256, GEMM_SMEM_BYTES>>>(
        xnh, wh + WOFF_W1, mlp_b1, nullptr, nullptr, midh, ROWS, 4 * EE, EE, 1, 1);
    // 9. out = midh @ mlp_w2 + mlp_b2 + h (fp32 final)
    tgemm_kernel<<<dim3(EE / 128, ROWS / 128), 256, GEMM_SMEM_BYTES>>>(
        midh, wh + WOFF_W2, mlp_b2, hbuf, out, nullptr, ROWS, EE, 4 * EE, 2, 0);
}